// round 14
// baseline (speedup 1.0000x reference)
#include <cuda_runtime.h>
#include <climits>

#define NB 32
#define H 512
#define W 512
#define C 3
#define OUT 400
#define THRESH 0.7f

#define BPB 32                      // bounds blocks per batch
#define ROWS_PER_BLK (H / BPB)      // 16
#define TB 256

// Per-block partial bbox: rmin, rmax, cmin, cmax. Plain-stored every launch.
__device__ int g_part[NB * BPB][4];

__global__ void bounds_kernel(const float* __restrict__ tensor) {
    int blk  = blockIdx.x;
    int b    = blk / BPB;
    int rb   = blk % BPB;
    int row0 = rb * ROWS_PER_BLK;

    const float4* base =
        (const float4*)(tensor + ((size_t)b * H + row0) * W);

    // Front-batched loads: 8 independent LDG.128 per thread (MLP=8).
    float4 v[8];
    #pragma unroll
    for (int k = 0; k < 8; k++)
        v[k] = base[threadIdx.x + k * TB];

    int rmin = INT_MAX, rmax = -1, cmin = INT_MAX, cmax = -1;

    #pragma unroll
    for (int k = 0; k < 8; k++) {
        int j = threadIdx.x + k * TB;
        int r = j >> 7;
        int c = (j & 127) << 2;
        bool any = false;
        if (v[k].x > THRESH) { any = true; cmin = min(cmin, c    ); cmax = max(cmax, c    ); }
        if (v[k].y > THRESH) { any = true; cmin = min(cmin, c + 1); cmax = max(cmax, c + 1); }
        if (v[k].z > THRESH) { any = true; cmin = min(cmin, c + 2); cmax = max(cmax, c + 2); }
        if (v[k].w > THRESH) { any = true; cmin = min(cmin, c + 3); cmax = max(cmax, c + 3); }
        if (any) {
            int rr = row0 + r;
            rmin = min(rmin, rr);
            rmax = max(rmax, rr);
        }
    }

    #pragma unroll
    for (int o = 16; o > 0; o >>= 1) {
        rmin = min(rmin, __shfl_xor_sync(0xFFFFFFFFu, rmin, o));
        rmax = max(rmax, __shfl_xor_sync(0xFFFFFFFFu, rmax, o));
        cmin = min(cmin, __shfl_xor_sync(0xFFFFFFFFu, cmin, o));
        cmax = max(cmax, __shfl_xor_sync(0xFFFFFFFFu, cmax, o));
    }

    __shared__ int s[4][TB / 32];
    int wid = threadIdx.x >> 5, lid = threadIdx.x & 31;
    if (lid == 0) { s[0][wid] = rmin; s[1][wid] = rmax; s[2][wid] = cmin; s[3][wid] = cmax; }
    __syncthreads();
    if (threadIdx.x == 0) {
        #pragma unroll
        for (int i = 1; i < TB / 32; i++) {
            rmin = min(rmin, s[0][i]); rmax = max(rmax, s[1][i]);
            cmin = min(cmin, s[2][i]); cmax = max(cmax, s[3][i]);
        }
        g_part[blk][0] = rmin;
        g_part[blk][1] = rmax;
        g_part[blk][2] = cmin;
        g_part[blk][3] = cmax;
    }
}

// Inline replica of _axis_coords (float32 op order preserved).
// Handles the all-False-mask case: jnp.argmax on all-False gives (0, n-1).
__device__ __forceinline__ void axis_coords(int lo, int hi, int i,
                                            int& i0g, int& i1g, float& w) {
    if (hi < lo) { lo = 0; hi = H - 1; }   // H == W == 512
    float size = (float)(hi - lo);
    float src  = ((float)i + 0.5f) * size / (float)OUT - 0.5f;
    float mx   = fmaxf(size - 1.0f, 0.0f);
    src = fminf(fmaxf(src, 0.0f), mx);
    int   i0 = (int)floorf(src);
    int   i1 = min(i0 + 1, max(hi - lo - 1, 0));
    w = src - (float)i0;
    i0g = lo + i0;
    i1g = lo + i1;
}

// ---- Resize: SUBS blocks per batch, 2 independent rows per iteration ----
#define SUBS 10                       // 32*10 = 320 blocks, 40 rows (20 pairs) each
#define RZTX 3
#define RZTY 128
#define RZTN (RZTX * RZTY)            // 384 threads
#define ROWWORDS (OUT * C)            // 1200

__global__ void resize_kernel(const float* __restrict__ img,
                              float* __restrict__ out) {
    int b   = blockIdx.x / SUBS;
    int sub = blockIdx.x - b * SUBS;
    int row_start = sub * 40;

    int ch  = threadIdx.x;                        // 0..2
    int yy  = threadIdx.y;                        // 0..127
    int tid = threadIdx.x + threadIdx.y * RZTX;   // linear, == 3*yy+ch

    __shared__ int  sb[4];
    __shared__ int4 sct[OUT];   // x = c0*C, y = c1*C, z = bits(wc)

    // Reduce the 32 per-block bbox partials for this batch (warp 0).
    if (tid < 32) {
        const int* p = g_part[b * BPB + tid];
        int rmin = p[0], rmax = p[1], cmin = p[2], cmax = p[3];
        #pragma unroll
        for (int o = 16; o > 0; o >>= 1) {
            rmin = min(rmin, __shfl_xor_sync(0xFFFFFFFFu, rmin, o));
            rmax = max(rmax, __shfl_xor_sync(0xFFFFFFFFu, rmax, o));
            cmin = min(cmin, __shfl_xor_sync(0xFFFFFFFFu, cmin, o));
            cmax = max(cmax, __shfl_xor_sync(0xFFFFFFFFu, cmax, o));
        }
        if (tid == 0) {
            sb[0] = rmin; sb[1] = rmax; sb[2] = cmin; sb[3] = cmax;
        }
    }
    __syncthreads();

    int rlo = sb[0], rhi = sb[1], clo = sb[2], chi = sb[3];

    // Column coord table in shared memory (built once per block).
    for (int i = tid; i < OUT; i += RZTN) {
        int c0, c1; float w;
        axis_coords(clo, chi, i, c0, c1, w);
        sct[i] = make_int4(c0 * C, c1 * C, __float_as_int(w), 0);
    }
    __syncthreads();

    const float* bimg = img + (size_t)b * (H * W * C);

    for (int pr = 0; pr < 20; pr++) {
        int rA = row_start + pr * 2;
        int rB = rA + 1;

        int r0a, r1a; float wra;
        axis_coords(rlo, rhi, rA, r0a, r1a, wra);
        int r0b, r1b; float wrb;
        axis_coords(rlo, rhi, rB, r0b, r1b, wrb);
        float omwra = 1.0f - wra;
        float omwrb = 1.0f - wrb;

        const float* pA = bimg + r0a * (W * C);
        const float* pB = bimg + r1a * (W * C);
        const float* pC = bimg + r0b * (W * C);
        const float* pD = bimg + r1b * (W * C);

        float* orowA = out + ((size_t)b * OUT + rA) * ROWWORDS;
        float* orowB = orowA + ROWWORDS;

        // 400 columns in 4 strides of 128 (last stride: 16 cols).
        // No division anywhere: c from threadIdx.y, ch from threadIdx.x.
        #pragma unroll
        for (int it = 0; it < 4; it++) {
            int c = it * RZTY + yy;
            if (it < 3 || c < OUT) {
                int4 t = sct[c];
                int o0 = t.x + ch;
                int o1 = t.y + ch;
                float wc   = __int_as_float(t.z);
                float omwc = 1.0f - wc;

                // 8 independent loads for two independent rows.
                float a00 = __ldg(pA + o0);
                float a01 = __ldg(pA + o1);
                float a10 = __ldg(pB + o0);
                float a11 = __ldg(pB + o1);
                float b00 = __ldg(pC + o0);
                float b01 = __ldg(pC + o1);
                float b10 = __ldg(pD + o0);
                float b11 = __ldg(pD + o1);

                float topA = a00 * omwc + a01 * wc;
                float botA = a10 * omwc + a11 * wc;
                float topB = b00 * omwc + b01 * wc;
                float botB = b10 * omwc + b11 * wc;

                int e = it * RZTN + tid;   // contiguous per warp
                orowA[e] = topA * omwra + botA * wra;
                orowB[e] = topB * omwrb + botB * wrb;
            }
        }
    }
}

extern "C" void kernel_launch(void* const* d_in, const int* in_sizes, int n_in,
                              void* d_out, int out_size) {
    // Input-order detection: image has 25,165,824 elems, tensor 8,388,608.
    const float* image  = (const float*)d_in[0];
    const float* tensor = (const float*)d_in[1];
    if (n_in >= 2 && in_sizes[0] < in_sizes[1]) {
        image  = (const float*)d_in[1];
        tensor = (const float*)d_in[0];
    }
    float* out = (float*)d_out;

    bounds_kernel<<<NB * BPB, TB>>>(tensor);

    dim3 rblock(RZTX, RZTY);
    resize_kernel<<<NB * SUBS, rblock>>>(image, out);
}

// round 15
// speedup vs baseline: 1.6177x; 1.6177x over previous
#include <cuda_runtime.h>
#include <climits>

#define NB 32
#define H 512
#define W 512
#define C 3
#define OUT 400
#define THRESH 0.7f

#define BPB 32                      // bounds blocks per batch
#define ROWS_PER_BLK (H / BPB)      // 16
#define TB 256

// Per-block partial bbox: rmin, rmax, cmin, cmax. Plain-stored every launch.
__device__ int g_part[NB * BPB][4];
// Coordinate tables (separate arrays: row loads are warp-uniform, col loads
// are 1-line coalesced — measured-good in R1).
__device__ int   g_i0[2][NB][OUT];     // axis 0 = rows, axis 1 = cols
__device__ int   g_i1[2][NB][OUT];
__device__ float g_wt[2][NB][OUT];

__global__ void bounds_kernel(const float* __restrict__ tensor) {
    int blk  = blockIdx.x;
    int b    = blk / BPB;
    int rb   = blk % BPB;
    int row0 = rb * ROWS_PER_BLK;

    const float4* base =
        (const float4*)(tensor + ((size_t)b * H + row0) * W);

    // Front-batched loads: 8 independent LDG.128 per thread (MLP=8).
    float4 v[8];
    #pragma unroll
    for (int k = 0; k < 8; k++)
        v[k] = base[threadIdx.x + k * TB];

    int rmin = INT_MAX, rmax = -1, cmin = INT_MAX, cmax = -1;

    #pragma unroll
    for (int k = 0; k < 8; k++) {
        int j = threadIdx.x + k * TB;
        int r = j >> 7;
        int c = (j & 127) << 2;
        bool any = false;
        if (v[k].x > THRESH) { any = true; cmin = min(cmin, c    ); cmax = max(cmax, c    ); }
        if (v[k].y > THRESH) { any = true; cmin = min(cmin, c + 1); cmax = max(cmax, c + 1); }
        if (v[k].z > THRESH) { any = true; cmin = min(cmin, c + 2); cmax = max(cmax, c + 2); }
        if (v[k].w > THRESH) { any = true; cmin = min(cmin, c + 3); cmax = max(cmax, c + 3); }
        if (any) {
            int rr = row0 + r;
            rmin = min(rmin, rr);
            rmax = max(rmax, rr);
        }
    }

    #pragma unroll
    for (int o = 16; o > 0; o >>= 1) {
        rmin = min(rmin, __shfl_xor_sync(0xFFFFFFFFu, rmin, o));
        rmax = max(rmax, __shfl_xor_sync(0xFFFFFFFFu, rmax, o));
        cmin = min(cmin, __shfl_xor_sync(0xFFFFFFFFu, cmin, o));
        cmax = max(cmax, __shfl_xor_sync(0xFFFFFFFFu, cmax, o));
    }

    __shared__ int s[4][TB / 32];
    int wid = threadIdx.x >> 5, lid = threadIdx.x & 31;
    if (lid == 0) { s[0][wid] = rmin; s[1][wid] = rmax; s[2][wid] = cmin; s[3][wid] = cmax; }
    __syncthreads();
    if (threadIdx.x == 0) {
        #pragma unroll
        for (int i = 1; i < TB / 32; i++) {
            rmin = min(rmin, s[0][i]); rmax = max(rmax, s[1][i]);
            cmin = min(cmin, s[2][i]); cmax = max(cmax, s[3][i]);
        }
        g_part[blk][0] = rmin;
        g_part[blk][1] = rmax;
        g_part[blk][2] = cmin;
        g_part[blk][3] = cmax;
    }
}

// Inline replica of _axis_coords (float32 op order preserved).
// Handles the all-False-mask case: jnp.argmax on all-False gives (0, n-1).
__device__ __forceinline__ void axis_coords(int lo, int hi, int i,
                                            int& i0g, int& i1g, float& w) {
    if (hi < lo) { lo = 0; hi = H - 1; }   // H == W == 512
    float size = (float)(hi - lo);
    float src  = ((float)i + 0.5f) * size / (float)OUT - 0.5f;
    float mx   = fmaxf(size - 1.0f, 0.0f);
    src = fminf(fmaxf(src, 0.0f), mx);
    int   i0 = (int)floorf(src);
    int   i1 = min(i0 + 1, max(hi - lo - 1, 0));
    w = src - (float)i0;
    i0g = lo + i0;
    i1g = lo + i1;
}

// One block per batch: reduce bbox partials, then fill both coord tables.
__global__ __launch_bounds__(256) void coords_kernel() {
    int b = blockIdx.x;
    __shared__ int sb[4];

    if (threadIdx.x < 32) {
        const int* p = g_part[b * BPB + threadIdx.x];   // BPB == 32
        int rmin = p[0], rmax = p[1], cmin = p[2], cmax = p[3];
        #pragma unroll
        for (int o = 16; o > 0; o >>= 1) {
            rmin = min(rmin, __shfl_xor_sync(0xFFFFFFFFu, rmin, o));
            rmax = max(rmax, __shfl_xor_sync(0xFFFFFFFFu, rmax, o));
            cmin = min(cmin, __shfl_xor_sync(0xFFFFFFFFu, cmin, o));
            cmax = max(cmax, __shfl_xor_sync(0xFFFFFFFFu, cmax, o));
        }
        if (threadIdx.x == 0) {
            sb[0] = rmin; sb[1] = rmax; sb[2] = cmin; sb[3] = cmax;
        }
    }
    __syncthreads();

    int rlo = sb[0], rhi = sb[1], clo = sb[2], chi = sb[3];

    for (int t = threadIdx.x; t < 2 * OUT; t += 256) {
        int axis = t / OUT;
        int i    = t - axis * OUT;
        int i0, i1; float w;
        if (axis == 0) {
            axis_coords(rlo, rhi, i, i0, i1, w);
        } else {
            axis_coords(clo, chi, i, i0, i1, w);
        }
        g_i0[axis][b][i] = i0;
        g_i1[axis][b][i] = i1;
        g_wt[axis][b][i] = w;
    }
}

// R1's measured-best resize: one thread per output pixel (29 regs, occ ~88%).
__global__ void resize_kernel(const float* __restrict__ img,
                              float* __restrict__ out) {
    int idx = blockIdx.x * blockDim.x + threadIdx.x;
    const int total = NB * OUT * OUT;
    if (idx >= total) return;

    int c = idx % OUT;
    int t = idx / OUT;
    int r = t % OUT;
    int b = t / OUT;

    int   r0 = g_i0[0][b][r];
    int   r1 = g_i1[0][b][r];
    float wr = g_wt[0][b][r];
    int   c0 = g_i0[1][b][c];
    int   c1 = g_i1[1][b][c];
    float wc = g_wt[1][b][c];

    const float* base = img + (size_t)b * H * W * C;
    const float* p00 = base + ((size_t)r0 * W + c0) * C;
    const float* p01 = base + ((size_t)r0 * W + c1) * C;
    const float* p10 = base + ((size_t)r1 * W + c0) * C;
    const float* p11 = base + ((size_t)r1 * W + c1) * C;

    float omwc = 1.0f - wc;
    float omwr = 1.0f - wr;

    float* o = out + (size_t)idx * C;
    #pragma unroll
    for (int ch = 0; ch < C; ch++) {
        float a00 = __ldg(p00 + ch);
        float a01 = __ldg(p01 + ch);
        float a10 = __ldg(p10 + ch);
        float a11 = __ldg(p11 + ch);
        float topv = a00 * omwc + a01 * wc;
        float botv = a10 * omwc + a11 * wc;
        o[ch] = topv * omwr + botv * wr;
    }
}

extern "C" void kernel_launch(void* const* d_in, const int* in_sizes, int n_in,
                              void* d_out, int out_size) {
    // Input-order detection: image has 25,165,824 elems, tensor 8,388,608.
    const float* image  = (const float*)d_in[0];
    const float* tensor = (const float*)d_in[1];
    if (n_in >= 2 && in_sizes[0] < in_sizes[1]) {
        image  = (const float*)d_in[1];
        tensor = (const float*)d_in[0];
    }
    float* out = (float*)d_out;

    bounds_kernel<<<NB * BPB, TB>>>(tensor);
    coords_kernel<<<NB, 256>>>();

    const int total = NB * OUT * OUT;
    resize_kernel<<<(total + 255) / 256, 256>>>(image, out);
}